// round 10
// baseline (speedup 1.0000x reference)
#include <cuda_runtime.h>
#include <cuda_fp16.h>
#include <math.h>
#include <stdint.h>

#define N_ATOMS 100000
#define IN_F    1008
#define KPAD    1024
#define H1      256
#define H2      192
#define H3      160
#define CALPHA  0.1f
#define MT      128
#define TPB     512
#define NT_MAX  ((N_ATOMS + MT - 1) / MT)       // 782
#define PAD_MAX ((NT_MAX + 5) * MT)

// ---------------- device scratch (static, no allocations) ----------------
__device__ int g_type[N_ATOMS];
__device__ int g_sorted[PAD_MAX];
__device__ int g_counts[5], g_poff[5], g_cursor[5], g_is64;
// fp16 weights, uint4-fragment order: [t][kc][n8][kp(2)][lane] uint4
__device__ uint2 g_W16_1[5 * H1 * KPAD / 4];
__device__ uint2 g_W16_2[5 * H2 * H1 / 4];
__device__ uint2 g_W16_3[5 * H3 * H2 / 4];
// fp16 fragment-order h1 [tile][ks(16)][bm(8)][lane(32)]
__device__ uint4 g_H1f[(size_t)(NT_MAX + 5) * 16 * 8 * 32];

// ---------------- helpers ----------------
__device__ __forceinline__ float celu_f(float x) {
    return x > 0.0f ? x : CALPHA * expm1f(x * (1.0f / CALPHA));
}
__device__ __forceinline__ uint32_t pack2(float a, float b) {
    __half2 h = __floats2half2_rn(a, b);
    return *reinterpret_cast<uint32_t*>(&h);
}
__device__ __forceinline__ void cp16(uint32_t dst, const void* src) {
    asm volatile("cp.async.cg.shared.global [%0], [%1], 16;"
                 :: "r"(dst), "l"(src) : "memory");
}
#define CP_COMMIT() asm volatile("cp.async.commit_group;" ::: "memory")
#define CP_WAIT0()  asm volatile("cp.async.wait_group 0;" ::: "memory")

#define MMA16(d, a, b0, b1) \
    asm volatile("mma.sync.aligned.m16n8k16.row.col.f32.f16.f16.f32 " \
                 "{%0,%1,%2,%3},{%4,%5,%6,%7},{%8,%9},{%0,%1,%2,%3};" \
                 : "+f"((d)[0]), "+f"((d)[1]), "+f"((d)[2]), "+f"((d)[3]) \
                 : "r"((a).x), "r"((a).y), "r"((a).z), "r"((a).w), \
                   "r"(b0), "r"(b1))

__device__ __forceinline__ uint4 ldsm4(uint32_t addr) {
    uint4 v;
    asm volatile("ldmatrix.sync.aligned.m8n8.x4.shared.b16 {%0,%1,%2,%3}, [%4];"
                 : "=r"(v.x), "=r"(v.y), "=r"(v.z), "=r"(v.w) : "r"(addr));
    return v;
}

// ---------------- plumbing ----------------
__global__ void k_init(const int* __restrict__ z32, float* out, int n_out) {
    int i = blockIdx.x * blockDim.x + threadIdx.x;
    if (i < n_out) out[i] = 0.0f;
    if (i < PAD_MAX) g_sorted[i] = -1;
    if (i == 0) {
        g_is64 = (z32[1] == 0 && z32[3] == 0 && z32[5] == 0 && z32[7] == 0) ? 1 : 0;
        for (int t = 0; t < 5; t++) { g_counts[t] = 0; g_cursor[t] = 0; }
    }
}
__device__ __forceinline__ int z_to_type(int zv) {
    return (zv == 1) ? 0 : (zv == 6) ? 1 : (zv == 7) ? 2 : (zv == 8) ? 3 : 4;
}

// weight permute into uint4-fragment order (KC=64), fp16
template<int KC>
__device__ __forceinline__ void prep_w(uint2* dst, const float* src,
                                       int NN, int KTOT, int KIN, int i) {
    constexpr int KS = KC / 16;
    const int lane = i & 31;
    const int ks   = (i >> 5) % KS;
    int rest = i / (32 * KS);
    const int n8 = rest % (NN / 8); rest /= (NN / 8);
    const int kc = rest % (KTOT / KC);
    const int t  = rest / (KTOT / KC);
    const int n = n8 * 8 + (lane >> 2);
    const int k0 = kc * KC + ks * 16 + 2 * (lane & 3);
    const int k1 = k0 + 8;
    const float* W = src + (size_t)t * KIN * NN;
    float v00 = (k0 < KIN)     ? W[(size_t)k0 * NN + n]       : 0.0f;
    float v01 = (k0 + 1 < KIN) ? W[(size_t)(k0 + 1) * NN + n] : 0.0f;
    float v10 = (k1 < KIN)     ? W[(size_t)k1 * NN + n]       : 0.0f;
    float v11 = (k1 + 1 < KIN) ? W[(size_t)(k1 + 1) * NN + n] : 0.0f;
    const int group = (t * (KTOT / KC) + kc) * (NN / 8) + n8;
    dst[(size_t)group * (KS * 32) + (ks >> 1) * 64 + lane * 2 + (ks & 1)] =
        make_uint2(pack2(v00, v01), pack2(v10, v11));
}

__global__ void k_count_prep(const int* __restrict__ z32,
                             const float* __restrict__ W1,
                             const float* __restrict__ W2,
                             const float* __restrict__ W3) {
    int i = blockIdx.x * blockDim.x + threadIdx.x;
    if (blockIdx.y == 0) {
        if (i >= N_ATOMS) return;
        int zv = g_is64 ? z32[2 * i] : z32[i];
        int t = z_to_type(zv);
        g_type[i] = t;
        atomicAdd(&g_counts[t], 1);
    } else {
        const int n1 = 5 * H1 * KPAD / 4, n2 = 5 * H2 * H1 / 4, n3 = 5 * H3 * H2 / 4;
        if (i < n1) prep_w<64>(g_W16_1, W1, H1, KPAD, IN_F, i);
        else if (i < n1 + n2) prep_w<64>(g_W16_2, W2, H2, H1, H1, i - n1);
        else if (i < n1 + n2 + n3) prep_w<64>(g_W16_3, W3, H3, H2, H2, i - n1 - n2);
    }
}

__global__ void k_scatter() {
    int i = blockIdx.x * blockDim.x + threadIdx.x;
    int off[5]; int acc = 0;
#pragma unroll
    for (int t = 0; t < 5; t++) {
        off[t] = acc;
        acc += ((g_counts[t] + MT - 1) / MT) * MT;
    }
    if (i == 0) {
#pragma unroll
        for (int t = 0; t < 5; t++) g_poff[t] = off[t];
    }
    if (i >= N_ATOMS) return;
    int t = g_type[i];
    int pos = off[t] + atomicAdd(&g_cursor[t], 1);
    g_sorted[pos] = i;
}

// ================= GEMM 1: fp32 features -> fp16 smem (swizzled) -> ldmatrix =================
// 512 threads = 16 warps as 4(M) x 4(N); warp tile 32 x 64; K-chunks of 64.
// A smem: fp16, 128 rows x 64 halves (128B/row), 16B chunk j swizzled: jsw = j ^ (row&7).
#define G1_SM_A   0                       // 2*16384 = 32768
#define G1_SM_B   32768                   // 2*2048 uint4 = 65536
#define G1_SM_IDS 98304                   // 128 ints
#define G1_SM_TOTAL 98816

__global__ void __launch_bounds__(TPB)
k_gemm1(const float* __restrict__ feat, const float* __restrict__ b1)
{
    constexpr int NCH = KPAD / 64;        // 16
    constexpr int NT8 = 8;

    const int t = blockIdx.y;
    const int cnt = g_counts[t];
    const int start = blockIdx.x * MT;
    if (start >= cnt) return;
    const int tile = (g_poff[t] >> 7) + blockIdx.x;

    extern __shared__ __align__(16) char smem[];
    uint4* sB4 = reinterpret_cast<uint4*>(smem + G1_SM_B);
    int*   sids = reinterpret_cast<int*>(smem + G1_SM_IDS);

    const int tid = threadIdx.x;
    const int wid = tid >> 5, lane = tid & 31;
    const int wm = wid & 3, wn = wid >> 2;
    const int g = lane >> 2, tig = lane & 3;

    if (tid < MT) sids[tid] = g_sorted[tile * MT + tid];
    __syncthreads();

    const uint32_t sA_u = (uint32_t)__cvta_generic_to_shared(smem);
    const uint32_t sB_u = (uint32_t)__cvta_generic_to_shared(sB4);
    const uint4* Bt = reinterpret_cast<const uint4*>(g_W16_1) + (size_t)t * (H1 * KPAD / 8);

    // staging role: this thread owns row arow, float quarter Q (16 floats/chunk)
    const int arow = tid & 127;
    const int Q = tid >> 7;
    const int myid = sids[arow];
    const float* arowp = (myid >= 0) ? (feat + (size_t)myid * IN_F + Q * 16) : feat;
    // swizzled STS addresses (fixed per thread, stage offset added later)
    const int jsw0 = (2 * Q) ^ (arow & 7);
    const int jsw1 = (2 * Q + 1) ^ (arow & 7);
    const uint32_t sts0 = sA_u + arow * 128 + jsw0 * 16;
    const uint32_t sts1 = sA_u + arow * 128 + jsw1 * 16;

    // ldmatrix addresses (fixed per thread up to ksl/stage)
    const int lrow = wm * 32 + (lane & 15);      // + mt*16
    const int ljhi = lane >> 4;                  // 0/1 -> k-low/high 8
    const int lxor = lrow & 7;                   // same for mt*16 offsets

    float acc[2][NT8][4];
#pragma unroll
    for (int i = 0; i < 2; i++)
#pragma unroll
        for (int j = 0; j < NT8; j++)
#pragma unroll
            for (int q = 0; q < 4; q++) acc[i][j][q] = 0.0f;

    float ra[16];
    auto ldgA = [&](int c) {
        const int k = c * 64 + Q * 16;
        if (myid >= 0 && k < IN_F) {
#pragma unroll
            for (int i = 0; i < 4; i++)
                *reinterpret_cast<float4*>(ra + 4 * i) =
                    *reinterpret_cast<const float4*>(arowp + c * 64 + 4 * i);
        } else {
#pragma unroll
            for (int i = 0; i < 16; i++) ra[i] = 0.0f;
        }
    };
    auto stsA = [&](int s) {
        uint4 v0, v1;
        v0.x = pack2(ra[0], ra[1]);   v0.y = pack2(ra[2], ra[3]);
        v0.z = pack2(ra[4], ra[5]);   v0.w = pack2(ra[6], ra[7]);
        v1.x = pack2(ra[8], ra[9]);   v1.y = pack2(ra[10], ra[11]);
        v1.z = pack2(ra[12], ra[13]); v1.w = pack2(ra[14], ra[15]);
        asm volatile("st.shared.v4.b32 [%0], {%1,%2,%3,%4};"
                     :: "r"(sts0 + s * 16384), "r"(v0.x), "r"(v0.y), "r"(v0.z), "r"(v0.w));
        asm volatile("st.shared.v4.b32 [%0], {%1,%2,%3,%4};"
                     :: "r"(sts1 + s * 16384), "r"(v1.x), "r"(v1.y), "r"(v1.z), "r"(v1.w));
    };
    auto issueB = [&](int c) {
        const uint4* b = Bt + (size_t)c * 2048;
        const int s = c & 1;
#pragma unroll
        for (int q = tid; q < 2048; q += TPB)
            cp16(sB_u + ((s * 2048 + q) << 4), b + q);
        CP_COMMIT();
    };

    ldgA(0);
    issueB(0);
    for (int c = 0; c < NCH; c++) {
        const int s = c & 1;
        stsA(s);
        if (c + 1 < NCH) ldgA(c + 1);
        CP_WAIT0();
        __syncthreads();
        if (c + 1 < NCH) issueB(c + 1);

        const uint32_t Abase = sA_u + s * 16384;
        const uint4* B = sB4 + s * 2048;
#pragma unroll
        for (int kp = 0; kp < 2; kp++) {
            uint4 av0[2], av1[2];
#pragma unroll
            for (int mt = 0; mt < 2; mt++) {
                const int row = lrow + mt * 16;
                const int j0 = ((2 * kp) * 2 + ljhi) ^ lxor;      // ksl=2kp
                const int j1 = ((2 * kp + 1) * 2 + ljhi) ^ lxor;  // ksl=2kp+1
                av0[mt] = ldsm4(Abase + row * 128 + j0 * 16);
                av1[mt] = ldsm4(Abase + row * 128 + j1 * 16);
            }
#pragma unroll
            for (int nt = 0; nt < NT8; nt++) {
                const uint4 bq = B[((wn * NT8 + nt) << 6) + (kp << 5) + lane];
#pragma unroll
                for (int mt = 0; mt < 2; mt++) {
                    MMA16(acc[mt][nt], av0[mt], bq.x, bq.y);
                    MMA16(acc[mt][nt], av1[mt], bq.z, bq.w);
                }
            }
        }
        __syncthreads();
    }

    // epilogue: bias+celu -> h1 fragments [ks16][bm8][lane32]
    uint4* Hout = g_H1f + (size_t)tile * 16 * 256;
    const float* bv = b1 + t * H1;
#pragma unroll
    for (int mt = 0; mt < 2; mt++) {
#pragma unroll
        for (int ntp = 0; ntp < NT8 / 2; ntp++) {
            const int nt = 2 * ntp;
            const int c0 = wn * 64 + nt * 8 + 2 * tig;
            const int c1 = c0 + 8;
            const float bb0 = __ldg(bv + c0), bb1 = __ldg(bv + c0 + 1);
            const float bb2 = __ldg(bv + c1), bb3 = __ldg(bv + c1 + 1);
            uint4 v;
            v.x = pack2(celu_f(acc[mt][nt][0] + bb0),     celu_f(acc[mt][nt][1] + bb1));
            v.y = pack2(celu_f(acc[mt][nt][2] + bb0),     celu_f(acc[mt][nt][3] + bb1));
            v.z = pack2(celu_f(acc[mt][nt + 1][0] + bb2), celu_f(acc[mt][nt + 1][1] + bb3));
            v.w = pack2(celu_f(acc[mt][nt + 1][2] + bb2), celu_f(acc[mt][nt + 1][3] + bb3));
            const int ks = wn * 4 + ntp;
            const int bm = wm * 2 + mt;
            Hout[(ks * 8 + bm) * 32 + lane] = v;
        }
    }
}

// ================= GEMM 2+3 fused: h1 -> h2 (smem) -> out =================
#define G2_SM_A   0
#define G2_SM_B   32768
#define G2_SM_H2  81920
#define G2_SM_IDS 131072
#define G2_SM_TOTAL 131584
#define CP_WAIT1()  asm volatile("cp.async.wait_group 1;" ::: "memory")

__global__ void __launch_bounds__(TPB)
k_gemm23(const int* __restrict__ batch32,
         const float* __restrict__ b2, const float* __restrict__ b3,
         const float* __restrict__ W4, const float* __restrict__ b4,
         float* __restrict__ out)
{
    const int t = blockIdx.y;
    const int cnt = g_counts[t];
    const int start = blockIdx.x * MT;
    if (start >= cnt) return;
    const int nact = min(MT, cnt - start);
    const int tile = (g_poff[t] >> 7) + blockIdx.x;

    extern __shared__ __align__(16) char smem[];
    uint4* sA   = reinterpret_cast<uint4*>(smem + G2_SM_A);
    uint4* sB4  = reinterpret_cast<uint4*>(smem + G2_SM_B);
    uint4* sH2  = reinterpret_cast<uint4*>(smem + G2_SM_H2);
    int*   sids = reinterpret_cast<int*>(smem + G2_SM_IDS);

    const int tid = threadIdx.x;
    const int wid = tid >> 5, lane = tid & 31;
    const int wm = wid & 3, wn = wid >> 2;
    const int g = lane >> 2, tig = lane & 3;

    if (tid < MT) sids[tid] = g_sorted[tile * MT + tid];
    __syncthreads();

    const uint32_t sA_u = (uint32_t)__cvta_generic_to_shared(sA);
    const uint32_t sB_u = (uint32_t)__cvta_generic_to_shared(sB4);

    // ---------- Layer 2: A = g_H1f, B = g_W16_2, NN=192, K=256 ----------
    {
        constexpr int NCH = 4, NT8 = 6, BCH = H2 * 8;
        const uint4* Asrc = g_H1f + (size_t)tile * 16 * 256;
        const uint4* Bt = reinterpret_cast<const uint4*>(g_W16_2) + (size_t)t * (H2 * H1 / 8);

        float acc[2][NT8][4];
#pragma unroll
        for (int i = 0; i < 2; i++)
#pragma unroll
            for (int j = 0; j < NT8; j++)
#pragma unroll
                for (int q = 0; q < 4; q++) acc[i][j][q] = 0.0f;

        auto issue = [&](int c) {
            const int s = c & 1;
            const uint4* a = Asrc + c * 1024;
#pragma unroll
            for (int q = tid; q < 1024; q += TPB)
                cp16(sA_u + ((s * 1024 + q) << 4), a + q);
            const uint4* b = Bt + (size_t)c * BCH;
#pragma unroll
            for (int q = tid; q < BCH; q += TPB)
                cp16(sB_u + ((s * BCH + q) << 4), b + q);
            CP_COMMIT();
        };

        issue(0);
        for (int c = 0; c < NCH; c++) {
            if (c + 1 < NCH) { issue(c + 1); CP_WAIT1(); }
            else             { CP_WAIT0(); }
            __syncthreads();
            const uint4* A = sA + (c & 1) * 1024;
            const uint4* B = sB4 + (c & 1) * BCH;
#pragma unroll
            for (int kp = 0; kp < 2; kp++) {
                uint4 av0[2], av1[2];
#pragma unroll
                for (int mt = 0; mt < 2; mt++) {
                    av0[mt] = A[((2 * kp) * 8 + wm * 2 + mt) * 32 + lane];
                    av1[mt] = A[((2 * kp + 1) * 8 + wm * 2 + mt) * 32 + lane];
                }
#pragma unroll
                for (int nt = 0; nt < NT8; nt++) {
                    const uint4 bq = B[((wn * NT8 + nt) << 6) + (kp << 5) + lane];
#pragma unroll
                    for (int mt = 0; mt < 2; mt++) {
                        MMA16(acc[mt][nt], av0[mt], bq.x, bq.y);
                        MMA16(acc[mt][nt], av1[mt], bq.z, bq.w);
                    }
                }
            }
            __syncthreads();
        }

        const float* bv = b2 + t * H2;
#pragma unroll
        for (int mt = 0; mt < 2; mt++) {
#pragma unroll
            for (int ntp = 0; ntp < NT8 / 2; ntp++) {
                const int nt = 2 * ntp;
                const int c0 = wn * (H2 / 4) + nt * 8 + 2 * tig;
                const int c1 = c0 + 8;
                const float bb0 = __ldg(bv + c0), bb1 = __ldg(bv + c0 + 1);
                const float bb2 = __ldg(bv + c1), bb3 = __ldg(bv + c1 + 1);
                uint4 v;
                v.x = pack2(celu_f(acc[mt][nt][0] + bb0),     celu_f(acc[mt][nt][1] + bb1));
                v.y = pack2(celu_f(acc[mt][nt][2] + bb0),     celu_f(acc[mt][nt][3] + bb1));
                v.z = pack2(celu_f(acc[mt][nt + 1][0] + bb2), celu_f(acc[mt][nt + 1][1] + bb3));
                v.w = pack2(celu_f(acc[mt][nt + 1][2] + bb2), celu_f(acc[mt][nt + 1][3] + bb3));
                const int ks = wn * (NT8 / 2) + ntp;
                const int bm = wm * 2 + mt;
                sH2[(ks * 8 + bm) * 32 + lane] = v;
            }
        }
    }
    __syncthreads();

    // ---------- Layer 3 + 4: A = sH2, B = g_W16_3, NN=160, K=192 ----------
    {
        constexpr int NCH = 3, NT8 = 5, BCH = H3 * 8;
        const uint4* Bt = reinterpret_cast<const uint4*>(g_W16_3) + (size_t)t * (H3 * H2 / 8);

        float acc[2][NT8][4];
#pragma unroll
        for (int i = 0; i < 2; i++)
#pragma unroll
            for (int j = 0; j < NT8; j++)
#pragma unroll
                for (int q = 0; q < 4; q++) acc[i][j][q] = 0.0f;

        auto issueB = [&](int c) {
            const uint4* b = Bt + (size_t)c * BCH;
#pragma unroll
            for (int q = tid; q < BCH; q += TPB)
                cp16(sB_u + (((c & 1) * BCH + q) << 4), b + q);
            CP_COMMIT();
        };

        issueB(0);
        for (int c = 0; c < NCH; c++) {
            if (c + 1 < NCH) { issueB(c + 1); CP_WAIT1(); }
            else             { CP_WAIT0(); }
            __syncthreads();
            const uint4* B = sB4 + (c & 1) * BCH;
#pragma unroll
            for (int kp = 0; kp < 2; kp++) {
                uint4 av0[2], av1[2];
#pragma unroll
                for (int mt = 0; mt < 2; mt++) {
                    av0[mt] = sH2[((c * 4 + 2 * kp) * 8 + wm * 2 + mt) * 32 + lane];
                    av1[mt] = sH2[((c * 4 + 2 * kp + 1) * 8 + wm * 2 + mt) * 32 + lane];
                }
#pragma unroll
                for (int nt = 0; nt < NT8; nt++) {
                    const uint4 bq = B[((wn * NT8 + nt) << 6) + (kp << 5) + lane];
#pragma unroll
                    for (int mt = 0; mt < 2; mt++) {
                        MMA16(acc[mt][nt], av0[mt], bq.x, bq.y);
                        MMA16(acc[mt][nt], av1[mt], bq.z, bq.w);
                    }
                }
            }
            __syncthreads();
        }

        float part[2][2] = {{0.f, 0.f}, {0.f, 0.f}};
        const float* b3v = b3 + t * H3;
        const float* w4v = W4 + t * H3;
#pragma unroll
        for (int nt = 0; nt < NT8; nt++) {
            const int c0 = wn * (H3 / 4) + nt * 8 + 2 * tig;
            const float bb0 = __ldg(b3v + c0), bb1 = __ldg(b3v + c0 + 1);
            const float w0  = __ldg(w4v + c0), w1  = __ldg(w4v + c0 + 1);
#pragma unroll
            for (int mt = 0; mt < 2; mt++) {
                part[mt][0] += celu_f(acc[mt][nt][0] + bb0) * w0
                             + celu_f(acc[mt][nt][1] + bb1) * w1;
                part[mt][1] += celu_f(acc[mt][nt][2] + bb0) * w0
                             + celu_f(acc[mt][nt][3] + bb1) * w1;
            }
        }
#pragma unroll
        for (int mt = 0; mt < 2; mt++)
#pragma unroll
            for (int rh = 0; rh < 2; rh++) {
                part[mt][rh] += __shfl_xor_sync(0xffffffffu, part[mt][rh], 1);
                part[mt][rh] += __shfl_xor_sync(0xffffffffu, part[mt][rh], 2);
            }
        if (tig == 0) {
            const float b4v = __ldg(b4 + t);
#pragma unroll
            for (int mt = 0; mt < 2; mt++)
#pragma unroll
                for (int rh = 0; rh < 2; rh++) {
                    const int row = wm * 32 + mt * 16 + rh * 8 + g;
                    if (row < nact) {
                        const int id = sids[row];
                        const int mol = g_is64 ? batch32[2 * id] : batch32[id];
                        atomicAdd(&out[mol], part[mt][rh] + (wn == 0 ? b4v : 0.0f));
                    }
                }
        }
    }
}

// ---------------- launch ----------------
extern "C" void kernel_launch(void* const* d_in, const int* in_sizes, int n_in,
                              void* d_out, int out_size) {
    const int*   z     = (const int*)  d_in[0];
    const float* feat  = (const float*)d_in[1];
    const int*   batch = (const int*)  d_in[2];
    const float* W1 = (const float*)d_in[4];
    const float* b1 = (const float*)d_in[5];
    const float* W2 = (const float*)d_in[6];
    const float* b2 = (const float*)d_in[7];
    const float* W3 = (const float*)d_in[8];
    const float* b3 = (const float*)d_in[9];
    const float* W4 = (const float*)d_in[10];
    const float* b4 = (const float*)d_in[11];
    float* out = (float*)d_out;

    cudaFuncSetAttribute(k_gemm1,  cudaFuncAttributeMaxDynamicSharedMemorySize, G1_SM_TOTAL);
    cudaFuncSetAttribute(k_gemm23, cudaFuncAttributeMaxDynamicSharedMemorySize, G2_SM_TOTAL);

    const int initN = (out_size > PAD_MAX) ? out_size : PAD_MAX;
    const int prepN = 5 * H1 * KPAD / 4 + 5 * H2 * H1 / 4 + 5 * H3 * H2 / 4;
    const int cpN = (prepN > N_ATOMS) ? prepN : N_ATOMS;

    k_init<<<(initN + 255) / 256, 256>>>(z, out, out_size);            // 1
    dim3 cpg((cpN + 255) / 256, 2);
    k_count_prep<<<cpg, 256>>>(z, W1, W2, W3);                         // 2
    k_scatter<<<(N_ATOMS + 255) / 256, 256>>>();                       // 3

    dim3 grid(NT_MAX, 5);
    k_gemm1<<<grid, TPB, G1_SM_TOTAL>>>(feat, b1);                     // 4 <- profiled
    k_gemm23<<<grid, TPB, G2_SM_TOTAL>>>(batch, b2, b3, W4, b4, out);  // 5
}

// round 11
// speedup vs baseline: 1.1279x; 1.1279x over previous
#include <cuda_runtime.h>
#include <cuda_fp16.h>
#include <math.h>
#include <stdint.h>

#define N_ATOMS 100000
#define IN_F    1008
#define KPAD    1024
#define H1      256
#define H2      192
#define H3      160
#define CALPHA  0.1f
#define MT      128
#define TPB     512
#define NT_MAX  ((N_ATOMS + MT - 1) / MT)       // 782
#define PAD_MAX ((NT_MAX + 5) * MT)

// ---------------- device scratch (static, no allocations) ----------------
__device__ int g_type[N_ATOMS];
__device__ int g_sorted[PAD_MAX];
__device__ int g_counts[5], g_poff[5], g_cursor[5], g_is64;
// fp16 weights, uint4-fragment order: [t][kc][n8][kp(2)][lane] uint4
__device__ uint2 g_W16_1[5 * H1 * KPAD / 4];
__device__ uint2 g_W16_2[5 * H2 * H1 / 4];
__device__ uint2 g_W16_3[5 * H3 * H2 / 4];
// fp16 fragment-order h1 [tile][ks(16)][bm(8)][lane(32)]
__device__ uint4 g_H1f[(size_t)(NT_MAX + 5) * 16 * 8 * 32];

// ---------------- helpers ----------------
__device__ __forceinline__ float celu_f(float x) {
    return x > 0.0f ? x : CALPHA * expm1f(x * (1.0f / CALPHA));
}
__device__ __forceinline__ uint32_t pack2(float a, float b) {
    __half2 h = __floats2half2_rn(a, b);
    return *reinterpret_cast<uint32_t*>(&h);
}
__device__ __forceinline__ void cp16(uint32_t dst, const void* src) {
    asm volatile("cp.async.cg.shared.global [%0], [%1], 16;"
                 :: "r"(dst), "l"(src) : "memory");
}
__device__ __forceinline__ void cp16z(uint32_t dst, const void* src, int valid) {
    asm volatile("cp.async.cg.shared.global [%0], [%1], 16, %2;"
                 :: "r"(dst), "l"(src), "r"(valid ? 16 : 0) : "memory");
}
#define CP_COMMIT() asm volatile("cp.async.commit_group;" ::: "memory")
#define CP_WAIT0()  asm volatile("cp.async.wait_group 0;" ::: "memory")
#define CP_WAIT1()  asm volatile("cp.async.wait_group 1;" ::: "memory")

#define MMA16(d, a, b0, b1) \
    asm volatile("mma.sync.aligned.m16n8k16.row.col.f32.f16.f16.f32 " \
                 "{%0,%1,%2,%3},{%4,%5,%6,%7},{%8,%9},{%0,%1,%2,%3};" \
                 : "+f"((d)[0]), "+f"((d)[1]), "+f"((d)[2]), "+f"((d)[3]) \
                 : "r"((a).x), "r"((a).y), "r"((a).z), "r"((a).w), \
                   "r"(b0), "r"(b1))

__device__ __forceinline__ uint4 ldsm4(uint32_t addr) {
    uint4 v;
    asm volatile("ldmatrix.sync.aligned.m8n8.x4.shared.b16 {%0,%1,%2,%3}, [%4];"
                 : "=r"(v.x), "=r"(v.y), "=r"(v.z), "=r"(v.w) : "r"(addr));
    return v;
}

// ---------------- plumbing ----------------
__global__ void k_init(const int* __restrict__ z32, float* out, int n_out) {
    int i = blockIdx.x * blockDim.x + threadIdx.x;
    if (i < n_out) out[i] = 0.0f;
    if (i < PAD_MAX) g_sorted[i] = -1;
    if (i == 0) {
        g_is64 = (z32[1] == 0 && z32[3] == 0 && z32[5] == 0 && z32[7] == 0) ? 1 : 0;
        for (int t = 0; t < 5; t++) { g_counts[t] = 0; g_cursor[t] = 0; }
    }
}
__device__ __forceinline__ int z_to_type(int zv) {
    return (zv == 1) ? 0 : (zv == 6) ? 1 : (zv == 7) ? 2 : (zv == 8) ? 3 : 4;
}

// weight permute into uint4-fragment order (KC=64), fp16
template<int KC>
__device__ __forceinline__ void prep_w(uint2* dst, const float* src,
                                       int NN, int KTOT, int KIN, int i) {
    constexpr int KS = KC / 16;
    const int lane = i & 31;
    const int ks   = (i >> 5) % KS;
    int rest = i / (32 * KS);
    const int n8 = rest % (NN / 8); rest /= (NN / 8);
    const int kc = rest % (KTOT / KC);
    const int t  = rest / (KTOT / KC);
    const int n = n8 * 8 + (lane >> 2);
    const int k0 = kc * KC + ks * 16 + 2 * (lane & 3);
    const int k1 = k0 + 8;
    const float* W = src + (size_t)t * KIN * NN;
    float v00 = (k0 < KIN)     ? W[(size_t)k0 * NN + n]       : 0.0f;
    float v01 = (k0 + 1 < KIN) ? W[(size_t)(k0 + 1) * NN + n] : 0.0f;
    float v10 = (k1 < KIN)     ? W[(size_t)k1 * NN + n]       : 0.0f;
    float v11 = (k1 + 1 < KIN) ? W[(size_t)(k1 + 1) * NN + n] : 0.0f;
    const int group = (t * (KTOT / KC) + kc) * (NN / 8) + n8;
    dst[(size_t)group * (KS * 32) + (ks >> 1) * 64 + lane * 2 + (ks & 1)] =
        make_uint2(pack2(v00, v01), pack2(v10, v11));
}

__global__ void k_count_prep(const int* __restrict__ z32,
                             const float* __restrict__ W1,
                             const float* __restrict__ W2,
                             const float* __restrict__ W3) {
    int i = blockIdx.x * blockDim.x + threadIdx.x;
    if (blockIdx.y == 0) {
        if (i >= N_ATOMS) return;
        int zv = g_is64 ? z32[2 * i] : z32[i];
        int t = z_to_type(zv);
        g_type[i] = t;
        atomicAdd(&g_counts[t], 1);
    } else {
        const int n1 = 5 * H1 * KPAD / 4, n2 = 5 * H2 * H1 / 4, n3 = 5 * H3 * H2 / 4;
        if (i < n1) prep_w<64>(g_W16_1, W1, H1, KPAD, IN_F, i);
        else if (i < n1 + n2) prep_w<64>(g_W16_2, W2, H2, H1, H1, i - n1);
        else if (i < n1 + n2 + n3) prep_w<64>(g_W16_3, W3, H3, H2, H2, i - n1 - n2);
    }
}

__global__ void k_scatter() {
    int i = blockIdx.x * blockDim.x + threadIdx.x;
    int off[5]; int acc = 0;
#pragma unroll
    for (int t = 0; t < 5; t++) {
        off[t] = acc;
        acc += ((g_counts[t] + MT - 1) / MT) * MT;
    }
    if (i == 0) {
#pragma unroll
        for (int t = 0; t < 5; t++) g_poff[t] = off[t];
    }
    if (i >= N_ATOMS) return;
    int t = g_type[i];
    int pos = off[t] + atomicAdd(&g_cursor[t], 1);
    g_sorted[pos] = i;
}

// ================= GEMM 1 =================
// fp32 features --cp.async--> A32 smem (dbuf) --convert pass--> A16 smem (single)
// --ldmatrix--> HMMA.  512 threads = 16 warps as 4(M) x 4(N); K-chunks of 64.
// A32: 128 rows x 64 fp32 (row stride 64 floats), float4 slot jsw = fq ^ (r&15)
// A16: 128 rows x 64 halves (128B/row), 16B chunk j swizzled jsw = j ^ (r&7)
#define G1_SM_A32 0                       // 2*32768 = 65536
#define G1_SM_A16 65536                   // 16384
#define G1_SM_B   81920                   // 2*2048 uint4 = 65536
#define G1_SM_IDS 147456                  // 128 ints
#define G1_SM_TOTAL 147968

__global__ void __launch_bounds__(TPB)
k_gemm1(const float* __restrict__ feat, const float* __restrict__ b1)
{
    constexpr int NCH = KPAD / 64;        // 16
    constexpr int NT8 = 8;

    const int t = blockIdx.y;
    const int cnt = g_counts[t];
    const int start = blockIdx.x * MT;
    if (start >= cnt) return;
    const int tile = (g_poff[t] >> 7) + blockIdx.x;

    extern __shared__ __align__(16) char smem[];
    float* sA32 = reinterpret_cast<float*>(smem + G1_SM_A32);
    uint4* sB4  = reinterpret_cast<uint4*>(smem + G1_SM_B);
    int*   sids = reinterpret_cast<int*>(smem + G1_SM_IDS);

    const int tid = threadIdx.x;
    const int wid = tid >> 5, lane = tid & 31;
    const int wm = wid & 3, wn = wid >> 2;
    const int g = lane >> 2, tig = lane & 3;

    if (tid < MT) sids[tid] = g_sorted[tile * MT + tid];
    __syncthreads();

    const uint32_t sA32_u = (uint32_t)__cvta_generic_to_shared(smem + G1_SM_A32);
    const uint32_t sA16_u = (uint32_t)__cvta_generic_to_shared(smem + G1_SM_A16);
    const uint32_t sB_u   = (uint32_t)__cvta_generic_to_shared(sB4);
    const uint4* Bt = reinterpret_cast<const uint4*>(g_W16_1) + (size_t)t * (H1 * KPAD / 8);

    // convert-pass role: row r, quarter Q (16 floats)
    const int crow = tid & 127;
    const int Q = tid >> 7;
    // ldmatrix addressing (as validated in R10)
    const int lrow = wm * 32 + (lane & 15);
    const int ljhi = lane >> 4;
    const int lxor = lrow & 7;

    float acc[2][NT8][4];
#pragma unroll
    for (int i = 0; i < 2; i++)
#pragma unroll
        for (int j = 0; j < NT8; j++)
#pragma unroll
            for (int q = 0; q < 4; q++) acc[i][j][q] = 0.0f;

    auto issue = [&](int c) {
        const int s = c & 1;
        // A32: 2048 float4, swizzled jsw = fq ^ (r&15)
#pragma unroll
        for (int q = tid; q < MT * 16; q += TPB) {
            const int r = q >> 4, fq = q & 15;
            const int id = sids[r];
            const int k = c * 64 + fq * 4;
            const int v = (id >= 0) && (k < IN_F);
            const float* src = feat + (v ? ((size_t)id * IN_F + k) : 0);
            const int jsw = fq ^ (r & 15);
            cp16z(sA32_u + ((((s * MT + r) << 6) + (jsw << 2)) << 2), src, v);
        }
        // B: 2048 uint4 (fragment order, contiguous)
        const uint4* b = Bt + (size_t)c * 2048;
#pragma unroll
        for (int q = tid; q < 2048; q += TPB)
            cp16(sB_u + ((s * 2048 + q) << 4), b + q);
        CP_COMMIT();
    };

    issue(0);
    for (int c = 0; c < NCH; c++) {
        const int s = c & 1;
        CP_WAIT0();
        __syncthreads();      // A32/B stage s ready; all warps done reading A16(c-1)

        // ---- convert pass: A32 stage s -> A16 (single buffer) ----
        {
            const float* A32 = sA32 + s * MT * 64 + crow * 64;
            float4 f0 = *reinterpret_cast<const float4*>(A32 + (((4 * Q + 0) ^ (crow & 15)) << 2));
            float4 f1 = *reinterpret_cast<const float4*>(A32 + (((4 * Q + 1) ^ (crow & 15)) << 2));
            float4 f2 = *reinterpret_cast<const float4*>(A32 + (((4 * Q + 2) ^ (crow & 15)) << 2));
            float4 f3 = *reinterpret_cast<const float4*>(A32 + (((4 * Q + 3) ^ (crow & 15)) << 2));
            uint4 v0, v1;
            v0.x = pack2(f0.x, f0.y); v0.y = pack2(f0.z, f0.w);
            v0.z = pack2(f1.x, f1.y); v0.w = pack2(f1.z, f1.w);
            v1.x = pack2(f2.x, f2.y); v1.y = pack2(f2.z, f2.w);
            v1.z = pack2(f3.x, f3.y); v1.w = pack2(f3.z, f3.w);
            const uint32_t d0 = sA16_u + crow * 128 + (((2 * Q) ^ (crow & 7)) << 4);
            const uint32_t d1 = sA16_u + crow * 128 + (((2 * Q + 1) ^ (crow & 7)) << 4);
            asm volatile("st.shared.v4.b32 [%0], {%1,%2,%3,%4};"
                         :: "r"(d0), "r"(v0.x), "r"(v0.y), "r"(v0.z), "r"(v0.w));
            asm volatile("st.shared.v4.b32 [%0], {%1,%2,%3,%4};"
                         :: "r"(d1), "r"(v1.x), "r"(v1.y), "r"(v1.z), "r"(v1.w));
        }
        __syncthreads();      // A16 ready; safe to overwrite A32/B stage s^1

        if (c + 1 < NCH) issue(c + 1);   // prefetch overlaps compute

        const uint4* B = sB4 + s * 2048;
#pragma unroll
        for (int kp = 0; kp < 2; kp++) {
            uint4 av0[2], av1[2];
#pragma unroll
            for (int mt = 0; mt < 2; mt++) {
                const int row = lrow + mt * 16;
                const int j0 = ((2 * kp) * 2 + ljhi) ^ lxor;
                const int j1 = ((2 * kp + 1) * 2 + ljhi) ^ lxor;
                av0[mt] = ldsm4(sA16_u + row * 128 + j0 * 16);
                av1[mt] = ldsm4(sA16_u + row * 128 + j1 * 16);
            }
#pragma unroll
            for (int nt = 0; nt < NT8; nt++) {
                const uint4 bq = B[((wn * NT8 + nt) << 6) + (kp << 5) + lane];
#pragma unroll
                for (int mt = 0; mt < 2; mt++) {
                    MMA16(acc[mt][nt], av0[mt], bq.x, bq.y);
                    MMA16(acc[mt][nt], av1[mt], bq.z, bq.w);
                }
            }
        }
    }

    // epilogue: bias+celu -> h1 fragments [ks16][bm8][lane32]
    uint4* Hout = g_H1f + (size_t)tile * 16 * 256;
    const float* bv = b1 + t * H1;
#pragma unroll
    for (int mt = 0; mt < 2; mt++) {
#pragma unroll
        for (int ntp = 0; ntp < NT8 / 2; ntp++) {
            const int nt = 2 * ntp;
            const int c0 = wn * 64 + nt * 8 + 2 * tig;
            const int c1 = c0 + 8;
            const float bb0 = __ldg(bv + c0), bb1 = __ldg(bv + c0 + 1);
            const float bb2 = __ldg(bv + c1), bb3 = __ldg(bv + c1 + 1);
            uint4 v;
            v.x = pack2(celu_f(acc[mt][nt][0] + bb0),     celu_f(acc[mt][nt][1] + bb1));
            v.y = pack2(celu_f(acc[mt][nt][2] + bb0),     celu_f(acc[mt][nt][3] + bb1));
            v.z = pack2(celu_f(acc[mt][nt + 1][0] + bb2), celu_f(acc[mt][nt + 1][1] + bb3));
            v.w = pack2(celu_f(acc[mt][nt + 1][2] + bb2), celu_f(acc[mt][nt + 1][3] + bb3));
            const int ks = wn * 4 + ntp;
            const int bm = wm * 2 + mt;
            Hout[(ks * 8 + bm) * 32 + lane] = v;
        }
    }
}

// ================= GEMM 2+3 fused: h1 -> h2 (smem) -> out =================
#define G2_SM_A   0
#define G2_SM_B   32768
#define G2_SM_H2  81920
#define G2_SM_IDS 131072
#define G2_SM_TOTAL 131584

__global__ void __launch_bounds__(TPB)
k_gemm23(const int* __restrict__ batch32,
         const float* __restrict__ b2, const float* __restrict__ b3,
         const float* __restrict__ W4, const float* __restrict__ b4,
         float* __restrict__ out)
{
    const int t = blockIdx.y;
    const int cnt = g_counts[t];
    const int start = blockIdx.x * MT;
    if (start >= cnt) return;
    const int nact = min(MT, cnt - start);
    const int tile = (g_poff[t] >> 7) + blockIdx.x;

    extern __shared__ __align__(16) char smem[];
    uint4* sA   = reinterpret_cast<uint4*>(smem + G2_SM_A);
    uint4* sB4  = reinterpret_cast<uint4*>(smem + G2_SM_B);
    uint4* sH2  = reinterpret_cast<uint4*>(smem + G2_SM_H2);
    int*   sids = reinterpret_cast<int*>(smem + G2_SM_IDS);

    const int tid = threadIdx.x;
    const int wid = tid >> 5, lane = tid & 31;
    const int wm = wid & 3, wn = wid >> 2;
    const int g = lane >> 2, tig = lane & 3;

    if (tid < MT) sids[tid] = g_sorted[tile * MT + tid];
    __syncthreads();

    const uint32_t sA_u = (uint32_t)__cvta_generic_to_shared(sA);
    const uint32_t sB_u = (uint32_t)__cvta_generic_to_shared(sB4);

    // ---------- Layer 2: A = g_H1f, B = g_W16_2, NN=192, K=256 ----------
    {
        constexpr int NCH = 4, NT8 = 6, BCH = H2 * 8;
        const uint4* Asrc = g_H1f + (size_t)tile * 16 * 256;
        const uint4* Bt = reinterpret_cast<const uint4*>(g_W16_2) + (size_t)t * (H2 * H1 / 8);

        float acc[2][NT8][4];
#pragma unroll
        for (int i = 0; i < 2; i++)
#pragma unroll
            for (int j = 0; j < NT8; j++)
#pragma unroll
                for (int q = 0; q < 4; q++) acc[i][j][q] = 0.0f;

        auto issue = [&](int c) {
            const int s = c & 1;
            const uint4* a = Asrc + c * 1024;
#pragma unroll
            for (int q = tid; q < 1024; q += TPB)
                cp16(sA_u + ((s * 1024 + q) << 4), a + q);
            const uint4* b = Bt + (size_t)c * BCH;
#pragma unroll
            for (int q = tid; q < BCH; q += TPB)
                cp16(sB_u + ((s * BCH + q) << 4), b + q);
            CP_COMMIT();
        };

        issue(0);
        for (int c = 0; c < NCH; c++) {
            if (c + 1 < NCH) { issue(c + 1); CP_WAIT1(); }
            else             { CP_WAIT0(); }
            __syncthreads();
            const uint4* A = sA + (c & 1) * 1024;
            const uint4* B = sB4 + (c & 1) * BCH;
#pragma unroll
            for (int kp = 0; kp < 2; kp++) {
                uint4 av0[2], av1[2];
#pragma unroll
                for (int mt = 0; mt < 2; mt++) {
                    av0[mt] = A[((2 * kp) * 8 + wm * 2 + mt) * 32 + lane];
                    av1[mt] = A[((2 * kp + 1) * 8 + wm * 2 + mt) * 32 + lane];
                }
#pragma unroll
                for (int nt = 0; nt < NT8; nt++) {
                    const uint4 bq = B[((wn * NT8 + nt) << 6) + (kp << 5) + lane];
#pragma unroll
                    for (int mt = 0; mt < 2; mt++) {
                        MMA16(acc[mt][nt], av0[mt], bq.x, bq.y);
                        MMA16(acc[mt][nt], av1[mt], bq.z, bq.w);
                    }
                }
            }
            __syncthreads();
        }

        const float* bv = b2 + t * H2;
#pragma unroll
        for (int mt = 0; mt < 2; mt++) {
#pragma unroll
            for (int ntp = 0; ntp < NT8 / 2; ntp++) {
                const int nt = 2 * ntp;
                const int c0 = wn * (H2 / 4) + nt * 8 + 2 * tig;
                const int c1 = c0 + 8;
                const float bb0 = __ldg(bv + c0), bb1 = __ldg(bv + c0 + 1);
                const float bb2 = __ldg(bv + c1), bb3 = __ldg(bv + c1 + 1);
                uint4 v;
                v.x = pack2(celu_f(acc[mt][nt][0] + bb0),     celu_f(acc[mt][nt][1] + bb1));
                v.y = pack2(celu_f(acc[mt][nt][2] + bb0),     celu_f(acc[mt][nt][3] + bb1));
                v.z = pack2(celu_f(acc[mt][nt + 1][0] + bb2), celu_f(acc[mt][nt + 1][1] + bb3));
                v.w = pack2(celu_f(acc[mt][nt + 1][2] + bb2), celu_f(acc[mt][nt + 1][3] + bb3));
                const int ks = wn * (NT8 / 2) + ntp;
                const int bm = wm * 2 + mt;
                sH2[(ks * 8 + bm) * 32 + lane] = v;
            }
        }
    }
    __syncthreads();

    // ---------- Layer 3 + 4: A = sH2, B = g_W16_3, NN=160, K=192 ----------
    {
        constexpr int NCH = 3, NT8 = 5, BCH = H3 * 8;
        const uint4* Bt = reinterpret_cast<const uint4*>(g_W16_3) + (size_t)t * (H3 * H2 / 8);

        float acc[2][NT8][4];
#pragma unroll
        for (int i = 0; i < 2; i++)
#pragma unroll
            for (int j = 0; j < NT8; j++)
#pragma unroll
                for (int q = 0; q < 4; q++) acc[i][j][q] = 0.0f;

        auto issueB = [&](int c) {
            const uint4* b = Bt + (size_t)c * BCH;
#pragma unroll
            for (int q = tid; q < BCH; q += TPB)
                cp16(sB_u + (((c & 1) * BCH + q) << 4), b + q);
            CP_COMMIT();
        };

        issueB(0);
        for (int c = 0; c < NCH; c++) {
            if (c + 1 < NCH) { issueB(c + 1); CP_WAIT1(); }
            else             { CP_WAIT0(); }
            __syncthreads();
            const uint4* B = sB4 + (c & 1) * BCH;
#pragma unroll
            for (int kp = 0; kp < 2; kp++) {
                uint4 av0[2], av1[2];
#pragma unroll
                for (int mt = 0; mt < 2; mt++) {
                    av0[mt] = sH2[((c * 4 + 2 * kp) * 8 + wm * 2 + mt) * 32 + lane];
                    av1[mt] = sH2[((c * 4 + 2 * kp + 1) * 8 + wm * 2 + mt) * 32 + lane];
                }
#pragma unroll
                for (int nt = 0; nt < NT8; nt++) {
                    const uint4 bq = B[((wn * NT8 + nt) << 6) + (kp << 5) + lane];
#pragma unroll
                    for (int mt = 0; mt < 2; mt++) {
                        MMA16(acc[mt][nt], av0[mt], bq.x, bq.y);
                        MMA16(acc[mt][nt], av1[mt], bq.z, bq.w);
                    }
                }
            }
            __syncthreads();
        }

        float part[2][2] = {{0.f, 0.f}, {0.f, 0.f}};
        const float* b3v = b3 + t * H3;
        const float* w4v = W4 + t * H3;
#pragma unroll
        for (int nt = 0; nt < NT8; nt++) {
            const int c0 = wn * (H3 / 4) + nt * 8 + 2 * tig;
            const float bb0 = __ldg(b3v + c0), bb1 = __ldg(b3v + c0 + 1);
            const float w0  = __ldg(w4v + c0), w1  = __ldg(w4v + c0 + 1);
#pragma unroll
            for (int mt = 0; mt < 2; mt++) {
                part[mt][0] += celu_f(acc[mt][nt][0] + bb0) * w0
                             + celu_f(acc[mt][nt][1] + bb1) * w1;
                part[mt][1] += celu_f(acc[mt][nt][2] + bb0) * w0
                             + celu_f(acc[mt][nt][3] + bb1) * w1;
            }
        }
#pragma unroll
        for (int mt = 0; mt < 2; mt++)
#pragma unroll
            for (int rh = 0; rh < 2; rh++) {
                part[mt][rh] += __shfl_xor_sync(0xffffffffu, part[mt][rh], 1);
                part[mt][rh] += __shfl_xor_sync(0xffffffffu, part[mt][rh], 2);
            }
        if (tig == 0) {
            const float b4v = __ldg(b4 + t);
#pragma unroll
            for (int mt = 0; mt < 2; mt++)
#pragma unroll
                for (int rh = 0; rh < 2; rh++) {
                    const int row = wm * 32 + mt * 16 + rh * 8 + g;
                    if (row < nact) {
                        const int id = sids[row];
                        const int mol = g_is64 ? batch32[2 * id] : batch32[id];
                        atomicAdd(&out[mol], part[mt][rh] + (wn == 0 ? b4v : 0.0f));
                    }
                }
        }
    }
}

// ---------------- launch ----------------
extern "C" void kernel_launch(void* const* d_in, const int* in_sizes, int n_in,
                              void* d_out, int out_size) {
    const int*   z     = (const int*)  d_in[0];
    const float* feat  = (const float*)d_in[1];
    const int*   batch = (const int*)  d_in[2];
    const float* W1 = (const float*)d_in[4];
    const float* b1 = (const float*)d_in[5];
    const float* W2 = (const float*)d_in[6];
    const float* b2 = (const float*)d_in[7];
    const float* W3 = (const float*)d_in[8];
    const float* b3 = (const float*)d_in[9];
    const float* W4 = (const float*)d_in[10];
    const float* b4 = (const float*)d_in[11];
    float* out = (float*)d_out;

    cudaFuncSetAttribute(k_gemm1,  cudaFuncAttributeMaxDynamicSharedMemorySize, G1_SM_TOTAL);
    cudaFuncSetAttribute(k_gemm23, cudaFuncAttributeMaxDynamicSharedMemorySize, G2_SM_TOTAL);

    const int initN = (out_size > PAD_MAX) ? out_size : PAD_MAX;
    const int prepN = 5 * H1 * KPAD / 4 + 5 * H2 * H1 / 4 + 5 * H3 * H2 / 4;
    const int cpN = (prepN > N_ATOMS) ? prepN : N_ATOMS;

    k_init<<<(initN + 255) / 256, 256>>>(z, out, out_size);            // 1
    dim3 cpg((cpN + 255) / 256, 2);
    k_count_prep<<<cpg, 256>>>(z, W1, W2, W3);                         // 2
    k_scatter<<<(N_ATOMS + 255) / 256, 256>>>();                       // 3

    dim3 grid(NT_MAX, 5);
    k_gemm1<<<grid, TPB, G1_SM_TOTAL>>>(feat, b1);                     // 4 <- profiled
    k_gemm23<<<grid, TPB, G2_SM_TOTAL>>>(batch, b2, b3, W4, b4, out);  // 5
}